// round 2
// baseline (speedup 1.0000x reference)
#include <cuda_runtime.h>
#include <cuda_fp16.h>
#include <cstdint>

// Problem constants
#define BATCH 8
#define CDIM 512
#define HW   1024
#define NPROTO 150
#define KPROTO 32
#define NK   4800   // NPROTO * KPROTO

// GEMM tiling
#define TM 128
#define TN 64
#define TK 32
#define NSTAGE 3
#define SA_STRIDE 40   // 32 + 8 pad (halves)
#define SB_STRIDE 40

// Scratch (allocation-free rule: __device__ globals)
__device__ __align__(16) __half g_imgN[BATCH * HW * CDIM];   // [b*HW+hw][c]
__device__ __align__(16) __half g_protoN[NK * CDIM];         // [n*K+k][c]

// ---------------------------------------------------------------------------
// Kernel 1: normalize proto_emb rows (N*K rows of 512) -> fp16
// ---------------------------------------------------------------------------
__global__ void proto_norm_kernel(const float* __restrict__ proto) {
    int gwid = (blockIdx.x * blockDim.x + threadIdx.x) >> 5;
    int lane = threadIdx.x & 31;
    if (gwid >= NK) return;
    const float4* row = reinterpret_cast<const float4*>(proto + (size_t)gwid * CDIM);
    float4 v[4];
    float ss = 0.f;
#pragma unroll
    for (int i = 0; i < 4; i++) {
        v[i] = row[lane + i * 32];
        ss += v[i].x * v[i].x + v[i].y * v[i].y + v[i].z * v[i].z + v[i].w * v[i].w;
    }
#pragma unroll
    for (int o = 16; o > 0; o >>= 1) ss += __shfl_xor_sync(0xffffffff, ss, o);
    float rn = rsqrtf(ss + 1e-12f);
    __half2* dst = reinterpret_cast<__half2*>(g_protoN + (size_t)gwid * CDIM);
#pragma unroll
    for (int i = 0; i < 4; i++) {
        __half2 h0 = __floats2half2_rn(v[i].x * rn, v[i].y * rn);
        __half2 h1 = __floats2half2_rn(v[i].z * rn, v[i].w * rn);
        dst[(lane + i * 32) * 2]     = h0;
        dst[(lane + i * 32) * 2 + 1] = h1;
    }
}

// ---------------------------------------------------------------------------
// Kernel 2: normalize image over C and transpose [B,C,H,W] -> [B*HW][C] fp16
// blockDim = (32, 8); grid = (HW/32, BATCH)
// ---------------------------------------------------------------------------
__global__ void img_norm_kernel(const float* __restrict__ img) {
    __shared__ float part[8][32];
    __shared__ float rn[32];
    __shared__ __half tile[32][520];   // 32 px x 512 c, padded

    int tx = threadIdx.x;   // hw within tile
    int ty = threadIdx.y;
    int b = blockIdx.y;
    int hw0 = blockIdx.x * 32;
    const float* base = img + (size_t)b * CDIM * HW + hw0 + tx;

    float ss = 0.f;
    for (int c = ty; c < CDIM; c += 8) {
        float v = base[(size_t)c * HW];
        ss += v * v;
    }
    part[ty][tx] = ss;
    __syncthreads();
    if (ty == 0) {
        float s = 0.f;
#pragma unroll
        for (int j = 0; j < 8; j++) s += part[j][tx];
        rn[tx] = rsqrtf(s + 1e-12f);
    }
    __syncthreads();
    float r = rn[tx];
    for (int c = ty; c < CDIM; c += 8) {
        float v = base[(size_t)c * HW];
        tile[tx][c] = __float2half(v * r);
    }
    __syncthreads();
    // coalesced write-out: warp (=ty) per pixel row, 4 iterations
    int lane = tx;
#pragma unroll
    for (int it = 0; it < 4; it++) {
        int p = it * 8 + ty;
        const uint4* s = reinterpret_cast<const uint4*>(&tile[p][0]);
        uint4 d0 = s[lane * 2];
        uint4 d1 = s[lane * 2 + 1];
        uint4* dst = reinterpret_cast<uint4*>(g_imgN + ((size_t)(b * HW + hw0 + p)) * CDIM);
        dst[lane * 2]     = d0;
        dst[lane * 2 + 1] = d1;
    }
}

// ---------------------------------------------------------------------------
// Kernel 3: fused GEMM + group max/mean + sigmoid
// 3-stage cp.async pipeline, one __syncthreads per K-chunk.
// ---------------------------------------------------------------------------
struct SMemOp {
    __half A[NSTAGE][TM * SA_STRIDE];   // 3 * 10240 halves = 30720 B
    __half B[NSTAGE][TN * SB_STRIDE];   // 3 *  5120 halves = 15360 B
};
union SMemU {
    SMemOp op;          // 46080 B
    float  C[TM][65];   // 33280 B
};

__device__ __forceinline__ void cp_async16(uint32_t dst, const void* src) {
    asm volatile("cp.async.cg.shared.global [%0], [%1], 16;\n" :: "r"(dst), "l"(src));
}

__device__ __forceinline__ void load_chunk(const __half* gA, const __half* gB,
                                           __half* sA, __half* sB, int k0, int tid) {
    int ar = tid >> 2;            // 0..63
    int ac = (tid & 3) * 8;       // half offset within 32-chunk
    uint32_t sa = (uint32_t)__cvta_generic_to_shared(sA);
    cp_async16(sa + ((ar)      * SA_STRIDE + ac) * 2, gA + (size_t)(ar)      * CDIM + k0 + ac);
    cp_async16(sa + ((ar + 64) * SA_STRIDE + ac) * 2, gA + (size_t)(ar + 64) * CDIM + k0 + ac);
    uint32_t sb = (uint32_t)__cvta_generic_to_shared(sB);
    cp_async16(sb + (ar * SB_STRIDE + ac) * 2,        gB + (size_t)ar * CDIM + k0 + ac);
    asm volatile("cp.async.commit_group;\n");
}

__global__ __launch_bounds__(256) void simgemm_kernel(float* __restrict__ out) {
    __shared__ SMemU sm;

    int tid  = threadIdx.x;
    int lane = tid & 31;
    int wid  = tid >> 5;
    int b    = blockIdx.z;
    int hw0  = blockIdx.y * TM;
    int col0 = blockIdx.x * TN;   // nk column base (2 whole protos)

    const __half* gA = g_imgN   + ((size_t)(b * HW + hw0)) * CDIM;
    const __half* gB = g_protoN + (size_t)col0 * CDIM;

    int wm = wid >> 2;            // 0..1 : 64-px slice
    int wn = wid & 3;             // 0..3 : 16-col slice
    int pxw = wm * 64;
    int clw = wn * 16;

    // ldmatrix per-lane coordinates
    int a_r = lane & 15;
    int a_k = (lane >> 4) * 8;
    int b_r = (lane & 7) + ((lane >> 4) << 3);
    int b_k = ((lane >> 3) & 1) * 8;

    float acc[4][2][4];
#pragma unroll
    for (int mt = 0; mt < 4; mt++)
#pragma unroll
        for (int nt = 0; nt < 2; nt++)
#pragma unroll
            for (int i = 0; i < 4; i++) acc[mt][nt][i] = 0.f;

    const int NCHUNK = CDIM / TK;  // 16

    // Prime pipeline: stages 0 and 1
    load_chunk(gA, gB, sm.op.A[0], sm.op.B[0], 0, tid);
    load_chunk(gA, gB, sm.op.A[1], sm.op.B[1], TK, tid);

    int stage = 0;
    for (int kc = 0; kc < NCHUNK; kc++) {
        // Make stage kc's data visible. One group (stage kc+1) may stay in
        // flight — except on the last iteration, where nothing newer was
        // committed, so we must drain fully.
        if (kc == NCHUNK - 1) {
            asm volatile("cp.async.wait_group 0;\n");
        } else {
            asm volatile("cp.async.wait_group 1;\n");
        }
        __syncthreads();   // also protects buffer (kc+2)%3 from iter kc-1 readers

        // Prefetch stage kc+2 (buffer last read at iteration kc-1)
        if (kc + 2 < NCHUNK) {
            int ps = stage + 2 >= NSTAGE ? stage + 2 - NSTAGE : stage + 2;
            load_chunk(gA, gB, sm.op.A[ps], sm.op.B[ps], (kc + 2) * TK, tid);
        }

        const __half* sA = sm.op.A[stage];
        const __half* sB = sm.op.B[stage];
#pragma unroll
        for (int ks = 0; ks < 2; ks++) {
            int kk = ks * 16;
            uint32_t af[4][4];
#pragma unroll
            for (int mt = 0; mt < 4; mt++) {
                uint32_t addr = (uint32_t)__cvta_generic_to_shared(
                    sA + (size_t)(pxw + mt * 16 + a_r) * SA_STRIDE + kk + a_k);
                asm volatile("ldmatrix.sync.aligned.m8n8.x4.shared.b16 {%0,%1,%2,%3}, [%4];"
                             : "=r"(af[mt][0]), "=r"(af[mt][1]), "=r"(af[mt][2]), "=r"(af[mt][3])
                             : "r"(addr));
            }
            uint32_t bf4[4];
            {
                uint32_t addr = (uint32_t)__cvta_generic_to_shared(
                    sB + (size_t)(clw + b_r) * SB_STRIDE + kk + b_k);
                asm volatile("ldmatrix.sync.aligned.m8n8.x4.shared.b16 {%0,%1,%2,%3}, [%4];"
                             : "=r"(bf4[0]), "=r"(bf4[1]), "=r"(bf4[2]), "=r"(bf4[3])
                             : "r"(addr));
            }
#pragma unroll
            for (int mt = 0; mt < 4; mt++)
#pragma unroll
                for (int nt = 0; nt < 2; nt++) {
                    asm volatile(
                        "mma.sync.aligned.m16n8k16.row.col.f32.f16.f16.f32 "
                        "{%0,%1,%2,%3}, {%4,%5,%6,%7}, {%8,%9}, {%0,%1,%2,%3};"
                        : "+f"(acc[mt][nt][0]), "+f"(acc[mt][nt][1]),
                          "+f"(acc[mt][nt][2]), "+f"(acc[mt][nt][3])
                        : "r"(af[mt][0]), "r"(af[mt][1]), "r"(af[mt][2]), "r"(af[mt][3]),
                          "r"(bf4[nt * 2]), "r"(bf4[nt * 2 + 1]));
                }
        }
        stage = stage + 1 == NSTAGE ? 0 : stage + 1;
    }
    __syncthreads();   // all compute done before aliasing smem as C

    // Epilogue: stash tile in shared (aliases op buffers)
#pragma unroll
    for (int mt = 0; mt < 4; mt++)
#pragma unroll
        for (int nt = 0; nt < 2; nt++) {
            int r = pxw + mt * 16 + (lane >> 2);
            int c = clw + nt * 8 + (lane & 3) * 2;
            sm.C[r][c]         = acc[mt][nt][0];
            sm.C[r][c + 1]     = acc[mt][nt][1];
            sm.C[r + 8][c]     = acc[mt][nt][2];
            sm.C[r + 8][c + 1] = acc[mt][nt][3];
        }
    __syncthreads();

    // Reduce over K=32 per proto: 256 threads = 128 px x 2 protos
    int px = tid >> 1;
    int nn = tid & 1;
    float mx = -1e30f, sum = 0.f;
#pragma unroll
    for (int j = 0; j < 32; j++) {
        float v = sm.C[px][nn * 32 + j];
        mx = fmaxf(mx, v);
        sum += v;
    }
    float sim  = 0.5f * mx + 0.5f * (sum * (1.0f / 32.0f));
    float mask = 1.0f / (1.0f + __expf(-sim));

    int ng = blockIdx.x * 2 + nn;
    size_t idx = ((size_t)(b * NPROTO + ng)) * HW + hw0 + px;
    out[idx] = mask;                                   // soft_mask (first output)
    out[idx + (size_t)BATCH * NPROTO * HW] = sim;      // sim (second output)
}

// ---------------------------------------------------------------------------
extern "C" void kernel_launch(void* const* d_in, const int* in_sizes, int n_in,
                              void* d_out, int out_size) {
    (void)in_sizes; (void)n_in; (void)out_size;
    const float* img   = (const float*)d_in[0];   // [8,512,32,32]
    const float* proto = (const float*)d_in[1];   // [150,32,512]
    float* out = (float*)d_out;

    proto_norm_kernel<<<NK / 8, 256>>>(proto);                 // 600 blocks, warp/row
    img_norm_kernel<<<dim3(HW / 32, BATCH), dim3(32, 8)>>>(img);
    simgemm_kernel<<<dim3(NPROTO / 2, HW / TM, BATCH), 256>>>(out);
}

// round 10
// speedup vs baseline: 1.0004x; 1.0004x over previous
#include <cuda_runtime.h>
#include <cuda_fp16.h>
#include <cstdint>

// Problem constants
#define BATCH 8
#define CDIM 512
#define HW   1024
#define NPROTO 150
#define KPROTO 32
#define NK   4800   // NPROTO * KPROTO

// GEMM tiling (mma.sync path — base ISA only; tcgen05 is rejected by this
// harness's ptxas target compute_103)
#define TM 128
#define TN 64
#define TK 32
#define NSTAGE 3
#define SA_STRIDE 40   // 32 + 8 pad (halves)
#define SB_STRIDE 40

// Scratch (allocation-free rule: __device__ globals)
__device__ __align__(16) __half g_imgN[BATCH * HW * CDIM];   // [b*HW+hw][c]
__device__ __align__(16) __half g_protoN[NK * CDIM];         // [n*K+k][c]

// ---------------------------------------------------------------------------
// Kernel 1 (fused prep): blocks [0,600) normalize proto rows; blocks
// [600, 600+256) normalize+transpose the image. 256 threads everywhere.
// ---------------------------------------------------------------------------
__global__ void prep_kernel(const float* __restrict__ proto,
                            const float* __restrict__ img) {
    __shared__ float part[8][32];
    __shared__ float rn[32];
    __shared__ __half tile[32][520];

    if (blockIdx.x < 600) {
        // ---- proto normalize: 8 warps/block, one row per warp ----
        int gwid = (blockIdx.x * 256 + threadIdx.x) >> 5;
        int lane = threadIdx.x & 31;
        const float4* row = reinterpret_cast<const float4*>(proto + (size_t)gwid * CDIM);
        float4 v[4];
        float ss = 0.f;
#pragma unroll
        for (int i = 0; i < 4; i++) {
            v[i] = row[lane + i * 32];
            ss += v[i].x * v[i].x + v[i].y * v[i].y + v[i].z * v[i].z + v[i].w * v[i].w;
        }
#pragma unroll
        for (int o = 16; o > 0; o >>= 1) ss += __shfl_xor_sync(0xffffffff, ss, o);
        float r = rsqrtf(ss + 1e-12f);
        __half2* dst = reinterpret_cast<__half2*>(g_protoN + (size_t)gwid * CDIM);
#pragma unroll
        for (int i = 0; i < 4; i++) {
            dst[(lane + i * 32) * 2]     = __floats2half2_rn(v[i].x * r, v[i].y * r);
            dst[(lane + i * 32) * 2 + 1] = __floats2half2_rn(v[i].z * r, v[i].w * r);
        }
        return;
    }

    // ---- image normalize + transpose ----
    int blk = blockIdx.x - 600;          // 0..255
    int tx = threadIdx.x & 31;           // hw within 32-px tile
    int ty = threadIdx.x >> 5;           // 0..7
    int b = blk >> 5;                    // 0..7
    int hw0 = (blk & 31) * 32;
    const float* base = img + (size_t)b * CDIM * HW + hw0 + tx;

    float ss = 0.f;
    for (int c = ty; c < CDIM; c += 8) {
        float v = base[(size_t)c * HW];
        ss += v * v;
    }
    part[ty][tx] = ss;
    __syncthreads();
    if (ty == 0) {
        float s = 0.f;
#pragma unroll
        for (int j = 0; j < 8; j++) s += part[j][tx];
        rn[tx] = rsqrtf(s + 1e-12f);
    }
    __syncthreads();
    float r = rn[tx];
    for (int c = ty; c < CDIM; c += 8) {
        float v = base[(size_t)c * HW];
        tile[tx][c] = __float2half(v * r);
    }
    __syncthreads();
#pragma unroll
    for (int it = 0; it < 4; it++) {
        int p = it * 8 + ty;
        const uint4* s = reinterpret_cast<const uint4*>(&tile[p][0]);
        uint4 d0 = s[tx * 2];
        uint4 d1 = s[tx * 2 + 1];
        uint4* dst = reinterpret_cast<uint4*>(g_imgN + ((size_t)(b * HW + hw0 + p)) * CDIM);
        dst[tx * 2]     = d0;
        dst[tx * 2 + 1] = d1;
    }
}

// ---------------------------------------------------------------------------
// Kernel 2: fused GEMM + group max/mean + sigmoid
// 3-stage cp.async pipeline, ONE __syncthreads per K-chunk.
// ---------------------------------------------------------------------------
struct SMemOp {
    __half A[NSTAGE][TM * SA_STRIDE];   // 3 * 10240 halves = 30720 B
    __half B[NSTAGE][TN * SB_STRIDE];   // 3 *  5120 halves = 15360 B
};
union SMemU {
    SMemOp op;          // 46080 B
    float  C[TM][65];   // 33280 B
};

__device__ __forceinline__ void cp_async16(uint32_t dst, const void* src) {
    asm volatile("cp.async.cg.shared.global [%0], [%1], 16;\n" :: "r"(dst), "l"(src));
}

__device__ __forceinline__ void load_chunk(const __half* gA, const __half* gB,
                                           __half* sA, __half* sB, int k0, int tid) {
    int ar = tid >> 2;            // 0..63
    int ac = (tid & 3) * 8;       // half offset within 32-chunk
    uint32_t sa = (uint32_t)__cvta_generic_to_shared(sA);
    cp_async16(sa + ((ar)      * SA_STRIDE + ac) * 2, gA + (size_t)(ar)      * CDIM + k0 + ac);
    cp_async16(sa + ((ar + 64) * SA_STRIDE + ac) * 2, gA + (size_t)(ar + 64) * CDIM + k0 + ac);
    uint32_t sb = (uint32_t)__cvta_generic_to_shared(sB);
    cp_async16(sb + (ar * SB_STRIDE + ac) * 2,        gB + (size_t)ar * CDIM + k0 + ac);
    asm volatile("cp.async.commit_group;\n");
}

__global__ __launch_bounds__(256) void simgemm_kernel(float* __restrict__ out) {
    __shared__ SMemU sm;

    int tid  = threadIdx.x;
    int lane = tid & 31;
    int wid  = tid >> 5;
    int b    = blockIdx.z;
    int hw0  = blockIdx.y * TM;
    int col0 = blockIdx.x * TN;   // nk column base (2 whole protos)

    const __half* gA = g_imgN   + ((size_t)(b * HW + hw0)) * CDIM;
    const __half* gB = g_protoN + (size_t)col0 * CDIM;

    int wm = wid >> 2;            // 0..1 : 64-px slice
    int wn = wid & 3;             // 0..3 : 16-col slice
    int pxw = wm * 64;
    int clw = wn * 16;

    // ldmatrix per-lane coordinates
    int a_r = lane & 15;
    int a_k = (lane >> 4) * 8;
    int b_r = (lane & 7) + ((lane >> 4) << 3);
    int b_k = ((lane >> 3) & 1) * 8;

    float acc[4][2][4];
#pragma unroll
    for (int mt = 0; mt < 4; mt++)
#pragma unroll
        for (int nt = 0; nt < 2; nt++)
#pragma unroll
            for (int i = 0; i < 4; i++) acc[mt][nt][i] = 0.f;

    const int NCHUNK = CDIM / TK;  // 16

    // Prime pipeline: stages 0 and 1
    load_chunk(gA, gB, sm.op.A[0], sm.op.B[0], 0, tid);
    load_chunk(gA, gB, sm.op.A[1], sm.op.B[1], TK, tid);

    int stage = 0;
    for (int kc = 0; kc < NCHUNK; kc++) {
        // Make stage kc's data visible. One group (stage kc+1) may stay in
        // flight — except on the last iteration, where nothing newer was
        // committed, so we must drain fully.
        if (kc == NCHUNK - 1) {
            asm volatile("cp.async.wait_group 0;\n");
        } else {
            asm volatile("cp.async.wait_group 1;\n");
        }
        __syncthreads();   // also protects buffer (kc+2)%3 from iter kc-1 readers

        // Prefetch stage kc+2 (its buffer was last read at iteration kc-1)
        if (kc + 2 < NCHUNK) {
            int ps = stage + 2 >= NSTAGE ? stage + 2 - NSTAGE : stage + 2;
            load_chunk(gA, gB, sm.op.A[ps], sm.op.B[ps], (kc + 2) * TK, tid);
        }

        const __half* sA = sm.op.A[stage];
        const __half* sB = sm.op.B[stage];
#pragma unroll
        for (int ks = 0; ks < 2; ks++) {
            int kk = ks * 16;
            uint32_t af[4][4];
#pragma unroll
            for (int mt = 0; mt < 4; mt++) {
                uint32_t addr = (uint32_t)__cvta_generic_to_shared(
                    sA + (size_t)(pxw + mt * 16 + a_r) * SA_STRIDE + kk + a_k);
                asm volatile("ldmatrix.sync.aligned.m8n8.x4.shared.b16 {%0,%1,%2,%3}, [%4];"
                             : "=r"(af[mt][0]), "=r"(af[mt][1]), "=r"(af[mt][2]), "=r"(af[mt][3])
                             : "r"(addr));
            }
            uint32_t bf4[4];
            {
                uint32_t addr = (uint32_t)__cvta_generic_to_shared(
                    sB + (size_t)(clw + b_r) * SB_STRIDE + kk + b_k);
                asm volatile("ldmatrix.sync.aligned.m8n8.x4.shared.b16 {%0,%1,%2,%3}, [%4];"
                             : "=r"(bf4[0]), "=r"(bf4[1]), "=r"(bf4[2]), "=r"(bf4[3])
                             : "r"(addr));
            }
#pragma unroll
            for (int mt = 0; mt < 4; mt++)
#pragma unroll
                for (int nt = 0; nt < 2; nt++) {
                    asm volatile(
                        "mma.sync.aligned.m16n8k16.row.col.f32.f16.f16.f32 "
                        "{%0,%1,%2,%3}, {%4,%5,%6,%7}, {%8,%9}, {%0,%1,%2,%3};"
                        : "+f"(acc[mt][nt][0]), "+f"(acc[mt][nt][1]),
                          "+f"(acc[mt][nt][2]), "+f"(acc[mt][nt][3])
                        : "r"(af[mt][0]), "r"(af[mt][1]), "r"(af[mt][2]), "r"(af[mt][3]),
                          "r"(bf4[nt * 2]), "r"(bf4[nt * 2 + 1]));
                }
        }
        stage = stage + 1 == NSTAGE ? 0 : stage + 1;
    }
    __syncthreads();   // all compute done before aliasing smem as C

    // Epilogue: stash tile in shared (aliases op buffers)
#pragma unroll
    for (int mt = 0; mt < 4; mt++)
#pragma unroll
        for (int nt = 0; nt < 2; nt++) {
            int r = pxw + mt * 16 + (lane >> 2);
            int c = clw + nt * 8 + (lane & 3) * 2;
            sm.C[r][c]         = acc[mt][nt][0];
            sm.C[r][c + 1]     = acc[mt][nt][1];
            sm.C[r + 8][c]     = acc[mt][nt][2];
            sm.C[r + 8][c + 1] = acc[mt][nt][3];
        }
    __syncthreads();

    // Reduce over K=32 per proto: 256 threads = 128 px x 2 protos
    int px = tid >> 1;
    int nn = tid & 1;
    float mx = -1e30f, sum = 0.f;
#pragma unroll
    for (int j = 0; j < 32; j++) {
        float v = sm.C[px][nn * 32 + j];
        mx = fmaxf(mx, v);
        sum += v;
    }
    float sim  = 0.5f * mx + 0.5f * (sum * (1.0f / 32.0f));
    float mask = 1.0f / (1.0f + __expf(-sim));

    int ng = blockIdx.x * 2 + nn;
    size_t idx = ((size_t)(b * NPROTO + ng)) * HW + hw0 + px;
    out[idx] = mask;                                   // soft_mask (first output)
    out[idx + (size_t)BATCH * NPROTO * HW] = sim;      // sim (second output)
}

// ---------------------------------------------------------------------------
extern "C" void kernel_launch(void* const* d_in, const int* in_sizes, int n_in,
                              void* d_out, int out_size) {
    (void)in_sizes; (void)n_in; (void)out_size;
    const float* img   = (const float*)d_in[0];   // [8,512,32,32]
    const float* proto = (const float*)d_in[1];   // [150,32,512]
    float* out = (float*)d_out;

    prep_kernel<<<600 + 256, 256>>>(proto, img);
    simgemm_kernel<<<dim3(NPROTO / 2, HW / TM, BATCH), 256>>>(out);
}